// round 15
// baseline (speedup 1.0000x reference)
#include <cuda_runtime.h>
#include <cuda_fp16.h>
#include <math.h>
#include <stdint.h>

#define T_TOK 8192
#define D_MOD 576
#define N_HEAD 9
#define HDIM 64
#define LAT 144
#define LATP 192
#define FF 1536
#define NE 7
#define SEQ 1024
#define ENT_CAP 17280

typedef __half hf;

// ---------------- fp32 scratch ----------------
__device__ __align__(128) float g_x2[T_TOK * D_MOD];
__device__ __align__(128) float g_h2f[T_TOK * D_MOD];
__device__ __align__(128) float g_shared[T_TOK * D_MOD];
__device__ __align__(128) float g_rout[T_TOK * 2 * D_MOD];
__device__ float g_w[T_TOK * 2];
__device__ int   g_top[T_TOK * 2];
__device__ int   g_cnt[NE];
__device__ int   g_offs[NE + 1];
__device__ int   g_cursor[NE];
__device__ int   g_entries[ENT_CAP];

// ---------------- fp16 activations ----------------
__device__ __align__(128) hf a_h[T_TOK * D_MOD];
__device__ __align__(128) hf a_ql[T_TOK * LATP];
__device__ __align__(128) hf a_kv[T_TOK * LATP];
__device__ __align__(128) hf a_q[T_TOK * D_MOD];
__device__ __align__(128) hf a_k[T_TOK * D_MOD];
__device__ __align__(128) hf a_v[T_TOK * D_MOD];
__device__ __align__(128) hf a_o[T_TOK * D_MOD];
__device__ __align__(128) hf a_h2[T_TOK * D_MOD];
__device__ __align__(128) hf a_ff[T_TOK * FF];
__device__ __align__(128) hf a_e[ENT_CAP * FF];

// ---------------- fp16 hi/lo weights (row-padded) -------------------------
__device__ __align__(128) hf w_qdh[256 * 576];
__device__ __align__(128) hf w_qdl[256 * 576];
__device__ __align__(128) hf w_kdh[256 * 576];
__device__ __align__(128) hf w_kdl[256 * 576];
__device__ __align__(128) hf w_quh[640 * 192];
__device__ __align__(128) hf w_qul[640 * 192];
__device__ __align__(128) hf w_kuh[640 * 192];
__device__ __align__(128) hf w_kul[640 * 192];
__device__ __align__(128) hf w_vuh[640 * 192];
__device__ __align__(128) hf w_vul[640 * 192];
__device__ __align__(128) hf w_oh[640 * 576];
__device__ __align__(128) hf w_ol[640 * 576];
__device__ __align__(128) hf w_sgh[1536 * 576];
__device__ __align__(128) hf w_sgl[1536 * 576];
__device__ __align__(128) hf w_suh[1536 * 576];
__device__ __align__(128) hf w_sul[1536 * 576];
__device__ __align__(128) hf w_sdh[640 * 1536];
__device__ __align__(128) hf w_sdl[640 * 1536];
__device__ __align__(128) hf w_rgh[NE * 1536 * 576];
__device__ __align__(128) hf w_rgl[NE * 1536 * 576];
__device__ __align__(128) hf w_ruh[NE * 1536 * 576];
__device__ __align__(128) hf w_rul[NE * 1536 * 576];
__device__ __align__(128) hf w_rdh[NE * 640 * 1536];
__device__ __align__(128) hf w_rdl[NE * 640 * 1536];

// ---------------- helpers ----------------
__device__ __forceinline__ void cp16(uint32_t dst, const void* src, uint32_t sz) {
    asm volatile("cp.async.cg.shared.global [%0], [%1], 16, %2;" :: "r"(dst), "l"(src), "r"(sz) : "memory");
}
__device__ __forceinline__ uint32_t smem_u32(const void* p) {
    uint32_t a;
    asm("{ .reg .u64 t; cvta.to.shared.u64 t, %1; cvt.u32.u64 %0, t; }" : "=r"(a) : "l"(p));
    return a;
}
__device__ __forceinline__ void mma_f16(float* c, const uint32_t* a, const uint32_t* b) {
    asm volatile(
        "mma.sync.aligned.m16n8k16.row.col.f32.f16.f16.f32 "
        "{%0,%1,%2,%3}, {%4,%5,%6,%7}, {%8,%9}, {%0,%1,%2,%3};"
        : "+f"(c[0]), "+f"(c[1]), "+f"(c[2]), "+f"(c[3])
        : "r"(a[0]), "r"(a[1]), "r"(a[2]), "r"(a[3]), "r"(b[0]), "r"(b[1]));
}
__device__ __forceinline__ void ldsm_x4(uint32_t* r, uint32_t addr) {
    asm volatile("ldmatrix.sync.aligned.m8n8.x4.shared.b16 {%0,%1,%2,%3}, [%4];"
        : "=r"(r[0]), "=r"(r[1]), "=r"(r[2]), "=r"(r[3]) : "r"(addr));
}
__device__ __forceinline__ void ldsm_x4_t(uint32_t* r, uint32_t addr) {
    asm volatile("ldmatrix.sync.aligned.m8n8.x4.trans.shared.b16 {%0,%1,%2,%3}, [%4];"
        : "=r"(r[0]), "=r"(r[1]), "=r"(r[2]), "=r"(r[3]) : "r"(addr));
}
__device__ __forceinline__ uint32_t pack_h2(float a, float b) {
    __half2 h = __floats2half2_rn(a, b);
    return *(uint32_t*)&h;
}

#define RS 40                   // GEMM smem row stride (80B): conflict-free for ldsm
#define NTH 256
#define GT_A (128 * RS * 2)     // 10240
#define GT_B (64 * RS * 2)      // 5120
#define GSTAGE (GT_A + 2 * GT_B)  // 20480
#define NSTAGE 3

// ================= single-B GEMM (128m x 64n, K-chunk 32, 3-stage) =========
// MODE: 0 fp32 | 1 fp32+Res | 2 fp16 out (zero-pad to ldo) | 5 MoE-down scatter fp32
template <int MODE>
__global__ void __launch_bounds__(NTH, 3)
gemm_mma(const hf* __restrict__ AF,
         const hf* __restrict__ BH, const hf* __restrict__ BL,
         float* __restrict__ Cout, const float* __restrict__ Res,
         hf* __restrict__ OF,
         int ldo, int N, int NC, long bstride) {
    extern __shared__ __align__(128) char smem_raw[];
    int tid = threadIdx.x, wid = tid >> 5, lane = tid & 31;
    int wm = wid >> 1, wn = wid & 1;          // 4(M) x 2(N)
    int nBase = blockIdx.x * 64, mBase = blockIdx.y * 128;
    const int KP = NC * 32;

    __shared__ int s_tok[128];
    __shared__ int s_info[2];
    if (MODE == 5) {
        if (tid == 0) {
            int lim = g_offs[NE];
            if (mBase >= lim) s_info[1] = 0;
            else {
                int e = 0;
                while (mBase >= g_offs[e + 1]) ++e;
                s_info[0] = e; s_info[1] = 1;
            }
        }
        __syncthreads();
        if (!s_info[1]) return;
        if (tid < 128) s_tok[tid] = g_entries[mBase + tid];
        __syncthreads();
        long eo = (long)s_info[0] * bstride;
        BH += eo; BL += eo;
    }

    uint32_t sb = smem_u32(smem_raw);

    auto prefetch = [&](int c) {
        if (c < NC) {
            uint32_t base = sb + (uint32_t)(c % NSTAGE) * GSTAGE;
            int k0 = c * 32;
#pragma unroll
            for (int i = 0; i < 2; ++i) {          // A: 128 rows x 4 segs
                int g2 = tid + i * NTH;
                int row = g2 >> 2, c4 = g2 & 3;
                uint32_t dst = base + row * (RS * 2) + c4 * 16;
                long aoff = (long)(mBase + row) * KP + k0 + c4 * 8;
                cp16(dst, AF + aoff, 16);
            }
            {                                      // B: 64 rows x 4 segs (hi+lo)
                int row = tid >> 2, c4 = tid & 3;
                uint32_t dst = base + GT_A + row * (RS * 2) + c4 * 16;
                long boff = (long)(nBase + row) * KP + k0 + c4 * 8;
                cp16(dst, BH + boff, 16);
                cp16(dst + GT_B, BL + boff, 16);
            }
        }
        asm volatile("cp.async.commit_group;" ::: "memory");
    };

    float acc[2][4][4];
#pragma unroll
    for (int i = 0; i < 2; ++i)
#pragma unroll
        for (int j = 0; j < 4; ++j)
#pragma unroll
            for (int k = 0; k < 4; ++k) acc[i][j][k] = 0.f;

    int g = lane >> 2, t4 = lane & 3;
    int lq = lane >> 3, l7 = lane & 7;
    int aro = l7 + (lq & 1) * 8, ako = (lq >> 1) * 8;
    int bro = l7 + (lq >> 1) * 8, bko = (lq & 1) * 8;

    prefetch(0);
    prefetch(1);
    prefetch(2);
    for (int c = 0; c < NC; ++c) {
        asm volatile("cp.async.wait_group %0;" :: "n"(NSTAGE - 1) : "memory");
        __syncthreads();
        uint32_t st = sb + (uint32_t)(c % NSTAGE) * GSTAGE;
        uint32_t Af = st, Bh = st + GT_A, Bl = Bh + GT_B;

#pragma unroll
        for (int kk = 0; kk < 2; ++kk) {
            int kb = kk * 16;
            uint32_t bh[4][2], bl[4][2];
#pragma unroll
            for (int pr = 0; pr < 2; ++pr) {
                uint32_t r[4];
                uint32_t off = (uint32_t)((wn * 32 + pr * 16 + bro) * RS + kb + bko) * 2;
                ldsm_x4(r, Bh + off);
                bh[pr * 2][0] = r[0]; bh[pr * 2][1] = r[1];
                bh[pr * 2 + 1][0] = r[2]; bh[pr * 2 + 1][1] = r[3];
                ldsm_x4(r, Bl + off);
                bl[pr * 2][0] = r[0]; bl[pr * 2][1] = r[1];
                bl[pr * 2 + 1][0] = r[2]; bl[pr * 2 + 1][1] = r[3];
            }
            uint32_t ah0[4], ah1[4];
            uint32_t off0 = (uint32_t)((wm * 32 + aro) * RS + kb + ako) * 2;
            uint32_t off1 = (uint32_t)((wm * 32 + 16 + aro) * RS + kb + ako) * 2;
            ldsm_x4(ah0, Af + off0);
            ldsm_x4(ah1, Af + off1);
#pragma unroll
            for (int nt = 0; nt < 4; ++nt) mma_f16(acc[0][nt], ah0, bh[nt]);
#pragma unroll
            for (int nt = 0; nt < 4; ++nt) mma_f16(acc[1][nt], ah1, bh[nt]);
#pragma unroll
            for (int nt = 0; nt < 4; ++nt) mma_f16(acc[0][nt], ah0, bl[nt]);
#pragma unroll
            for (int nt = 0; nt < 4; ++nt) mma_f16(acc[1][nt], ah1, bl[nt]);
        }
        __syncthreads();
        prefetch(c + NSTAGE);
    }

#pragma unroll
    for (int mt = 0; mt < 2; ++mt) {
#pragma unroll
        for (int nt = 0; nt < 4; ++nt) {
#pragma unroll
            for (int hh = 0; hh < 2; ++hh) {
                int lrow = wm * 32 + mt * 16 + g + hh * 8;
                int col = wn * 32 + nt * 8 + t4 * 2;
                float v0 = acc[mt][nt][hh * 2 + 0];
                float v1 = acc[mt][nt][hh * 2 + 1];
                long row = (long)(mBase + lrow);
                int c0 = nBase + col;
                if (MODE == 0 || MODE == 1) {
                    if (c0 < N) {
                        float a = v0, b = v1;
                        if (MODE == 1) {
                            a += Res[row * N + c0];
                            b += Res[row * N + c0 + 1];
                        }
                        Cout[row * N + c0] = a;
                        Cout[row * N + c0 + 1] = b;
                    }
                } else if (MODE == 2) {
                    if (c0 < ldo) {
                        long orow = row * ldo;
                        OF[orow + c0]     = __float2half_rn((c0 < N) ? v0 : 0.f);
                        OF[orow + c0 + 1] = __float2half_rn((c0 + 1 < N) ? v1 : 0.f);
                    }
                } else {
                    int v = s_tok[lrow];
                    if (v >= 0 && c0 < N) {
                        long orow = (long)v * D_MOD;
                        g_rout[orow + c0] = v0;
                        g_rout[orow + c0 + 1] = v1;
                    }
                }
            }
        }
    }
}

// ================= dual-B GEMM (128m x 32n per B, K-chunk 32, 3-stage) =====
#define DT_B32 (32 * RS * 2)         // 2560
#define DSTAGE (GT_A + 4 * DT_B32)   // 20480

template <int DM>
__global__ void __launch_bounds__(NTH, 3)
dual_mma(const hf* __restrict__ AF,
         const hf* __restrict__ B1H, const hf* __restrict__ B1L,
         const hf* __restrict__ B2H, const hf* __restrict__ B2L,
         hf* __restrict__ OF1, hf* __restrict__ OF2,
         int ldo, int N, int NC, long bstride) {
    extern __shared__ __align__(128) char smem_raw[];
    int tid = threadIdx.x, wid = tid >> 5, lane = tid & 31;
    int wm = wid >> 1, wn = wid & 1;          // 4(M) x 2(N of 16)
    int nBase = blockIdx.x * 32, mBase = blockIdx.y * 128;
    const int KP = NC * 32;

    __shared__ int s_tok[128];
    __shared__ int s_info[2];
    if (DM == 2) {
        if (tid == 0) {
            int lim = g_offs[NE];
            if (mBase >= lim) s_info[1] = 0;
            else {
                int e = 0;
                while (mBase >= g_offs[e + 1]) ++e;
                s_info[0] = e; s_info[1] = 1;
            }
        }
        __syncthreads();
        if (!s_info[1]) return;
        if (tid < 128) s_tok[tid] = g_entries[mBase + tid];
        __syncthreads();
        long eo = (long)s_info[0] * bstride;
        B1H += eo; B1L += eo; B2H += eo; B2L += eo;
    }

    uint32_t sb = smem_u32(smem_raw);

    auto prefetch = [&](int c) {
        if (c < NC) {
            uint32_t base = sb + (uint32_t)(c % NSTAGE) * DSTAGE;
            int k0 = c * 32;
#pragma unroll
            for (int i = 0; i < 2; ++i) {          // A: 128 rows x 4 segs
                int g2 = tid + i * NTH;
                int row = g2 >> 2, c4 = g2 & 3;
                uint32_t dst = base + row * (RS * 2) + c4 * 16;
                long aoff; uint32_t sz = 16;
                if (DM == 2) {
                    int v = s_tok[row];
                    if (v < 0) { sz = 0; aoff = 0; }
                    else aoff = (long)(v >> 1) * KP + k0 + c4 * 8;
                } else {
                    aoff = (long)(mBase + row) * KP + k0 + c4 * 8;
                }
                cp16(dst, AF + aoff, sz);
            }
            {                                      // B: 4 matrices x 32 rows x 4 segs = 512
#pragma unroll
                for (int i = 0; i < 2; ++i) {
                    int idx = tid + i * NTH;
                    int m = idx >> 7, rem = idx & 127;
                    int row = rem >> 2, c4 = rem & 3;
                    const hf* bp = (m == 0) ? B1H : (m == 1) ? B1L : (m == 2) ? B2H : B2L;
                    uint32_t dst = base + GT_A + (uint32_t)m * DT_B32 + row * (RS * 2) + c4 * 16;
                    long boff = (long)(nBase + row) * KP + k0 + c4 * 8;
                    cp16(dst, bp + boff, 16);
                }
            }
        }
        asm volatile("cp.async.commit_group;" ::: "memory");
    };

    float ac1[2][2][4], ac2[2][2][4];
#pragma unroll
    for (int i = 0; i < 2; ++i)
#pragma unroll
        for (int j = 0; j < 2; ++j)
#pragma unroll
            for (int k = 0; k < 4; ++k) { ac1[i][j][k] = 0.f; ac2[i][j][k] = 0.f; }

    int g = lane >> 2, t4 = lane & 3;
    int lq = lane >> 3, l7 = lane & 7;
    int aro = l7 + (lq & 1) * 8, ako = (lq >> 1) * 8;
    int bro = l7 + (lq >> 1) * 8, bko = (lq & 1) * 8;

    prefetch(0);
    prefetch(1);
    prefetch(2);
    for (int c = 0; c < NC; ++c) {
        asm volatile("cp.async.wait_group %0;" :: "n"(NSTAGE - 1) : "memory");
        __syncthreads();
        uint32_t st = sb + (uint32_t)(c % NSTAGE) * DSTAGE;
        uint32_t Af = st;
        uint32_t B1 = st + GT_A, B2 = B1 + 2 * DT_B32;

#pragma unroll
        for (int kk = 0; kk < 2; ++kk) {
            int kb = kk * 16;
            uint32_t b1h[2][2], b1l[2][2], b2h[2][2], b2l[2][2];
            {
                uint32_t off = (uint32_t)((wn * 16 + bro) * RS + kb + bko) * 2;
                uint32_t r[4];
                ldsm_x4(r, B1 + off);
                b1h[0][0] = r[0]; b1h[0][1] = r[1]; b1h[1][0] = r[2]; b1h[1][1] = r[3];
                ldsm_x4(r, B1 + DT_B32 + off);
                b1l[0][0] = r[0]; b1l[0][1] = r[1]; b1l[1][0] = r[2]; b1l[1][1] = r[3];
                ldsm_x4(r, B2 + off);
                b2h[0][0] = r[0]; b2h[0][1] = r[1]; b2h[1][0] = r[2]; b2h[1][1] = r[3];
                ldsm_x4(r, B2 + DT_B32 + off);
                b2l[0][0] = r[0]; b2l[0][1] = r[1]; b2l[1][0] = r[2]; b2l[1][1] = r[3];
            }
#pragma unroll
            for (int mt = 0; mt < 2; ++mt) {
                uint32_t ah[4];
                uint32_t off = (uint32_t)((wm * 32 + mt * 16 + aro) * RS + kb + ako) * 2;
                ldsm_x4(ah, Af + off);
#pragma unroll
                for (int nt = 0; nt < 2; ++nt) mma_f16(ac1[mt][nt], ah, b1h[nt]);
#pragma unroll
                for (int nt = 0; nt < 2; ++nt) mma_f16(ac2[mt][nt], ah, b2h[nt]);
#pragma unroll
                for (int nt = 0; nt < 2; ++nt) mma_f16(ac1[mt][nt], ah, b1l[nt]);
#pragma unroll
                for (int nt = 0; nt < 2; ++nt) mma_f16(ac2[mt][nt], ah, b2l[nt]);
            }
        }
        __syncthreads();
        prefetch(c + NSTAGE);
    }

#pragma unroll
    for (int mt = 0; mt < 2; ++mt) {
#pragma unroll
        for (int nt = 0; nt < 2; ++nt) {
#pragma unroll
            for (int hh = 0; hh < 2; ++hh) {
                int lrow = wm * 32 + mt * 16 + g + hh * 8;
                int col = wn * 16 + nt * 8 + t4 * 2;
                float u0 = ac1[mt][nt][hh * 2 + 0];
                float u1 = ac1[mt][nt][hh * 2 + 1];
                float v0 = ac2[mt][nt][hh * 2 + 0];
                float v1 = ac2[mt][nt][hh * 2 + 1];
                long row = (long)(mBase + lrow);
                int c0 = nBase + col;
                if (DM == 0) {
                    if (c0 < ldo) {
                        long orow = row * ldo;
                        OF1[orow + c0]     = __float2half_rn((c0 < N) ? u0 : 0.f);
                        OF1[orow + c0 + 1] = __float2half_rn((c0 + 1 < N) ? u1 : 0.f);
                        OF2[orow + c0]     = __float2half_rn((c0 < N) ? v0 : 0.f);
                        OF2[orow + c0 + 1] = __float2half_rn((c0 + 1 < N) ? v1 : 0.f);
                    }
                } else {
                    float o0 = (u0 / (1.f + __expf(-u0))) * v0;
                    float o1 = (u1 / (1.f + __expf(-u1))) * v1;
                    long orow = row * ldo;
                    OF1[orow + c0]     = __float2half_rn(o0);
                    OF1[orow + c0 + 1] = __float2half_rn(o1);
                }
            }
        }
    }
}

// ---- fast fp32 -> padded fp16 hi/lo: 8 elems/thread ----
__global__ void cvt_w8(const float* __restrict__ S, hf* __restrict__ H,
                       hf* __restrict__ L, int R, int K, int Kp, long total8) {
    long i = (long)blockIdx.x * blockDim.x + threadIdx.x;
    if (i >= total8) return;
    long i8 = i * 8;
    int r = (int)(i8 / Kp), c = (int)(i8 % Kp);
    uint4 ho, lo;
    if (r < R && c < K) {
        const float* src = S + (long)r * K + c;
        float4 v0 = *(const float4*)src;
        float4 v1 = *(const float4*)(src + 4);
        float vv[8] = {v0.x, v0.y, v0.z, v0.w, v1.x, v1.y, v1.z, v1.w};
        hf hh_[8], ll_[8];
#pragma unroll
        for (int j = 0; j < 8; ++j) {
            hf h = __float2half_rn(vv[j]);
            hh_[j] = h;
            ll_[j] = __float2half_rn(vv[j] - __half2float(h));
        }
        ho = *(uint4*)hh_;
        lo = *(uint4*)ll_;
    } else {
        ho = make_uint4(0, 0, 0, 0);
        lo = ho;
    }
    *(uint4*)(H + i8) = ho;
    *(uint4*)(L + i8) = lo;
}

// ---- rmsnorm ----
__global__ void rmsnorm_kernel(const float* __restrict__ x, const float* __restrict__ w,
                               float* __restrict__ outf, hf* __restrict__ outh) {
    int t = blockIdx.x;
    int tid = threadIdx.x;
    const float* xr = x + (size_t)t * D_MOD;
    float v0 = xr[tid], v1 = xr[tid + 192], v2 = xr[tid + 384];
    float ss = v0 * v0 + v1 * v1 + v2 * v2;
    for (int o = 16; o; o >>= 1) ss += __shfl_xor_sync(0xffffffffu, ss, o);
    __shared__ float red[8];
    int wid = tid >> 5, lane = tid & 31;
    if (lane == 0) red[wid] = ss;
    __syncthreads();
    if (tid == 0) {
        float s = 0.f;
        for (int i = 0; i < 6; ++i) s += red[i];
        red[0] = rsqrtf(s / (float)D_MOD + 1e-5f);
    }
    __syncthreads();
    float r = red[0];
    size_t bt = (size_t)t * D_MOD;
    float vv[3] = {v0, v1, v2};
#pragma unroll
    for (int u = 0; u < 3; ++u) {
        int c = tid + u * 192;
        float v = vv[u] * r * w[c];
        if (outf) outf[bt + c] = v;
        outh[bt + c] = __float2half_rn(v);
    }
}

// ---- RoPE: in-place on fp16 q/k ----
__global__ void rope_kernel(hf* __restrict__ q, hf* __restrict__ k) {
    int t = blockIdx.x;
    int tid = threadIdx.x;
    int h = tid >> 5, i = tid & 31;
    int pos = t & (SEQ - 1);
    float inv = __expf(-(float)i * 0.28782313662425572f);
    float f = (float)pos * inv;
    float sv, cv;
    sincosf(f, &sv, &cv);
    size_t base = (size_t)t * D_MOD + h * HDIM + i;
    float q1 = __half2float(q[base]), q2 = __half2float(q[base + 32]);
    q[base]      = __float2half_rn(q1 * cv - q2 * sv);
    q[base + 32] = __float2half_rn(q2 * cv + q1 * sv);
    float k1 = __half2float(k[base]), k2 = __half2float(k[base + 32]);
    k[base]      = __float2half_rn(k1 * cv - k2 * sv);
    k[base + 32] = __float2half_rn(k2 * cv + k1 * sv);
}

// ---- flash attention (own layout, ARS=72) ----
#define ARS 72
#define ATH 256
#define AQ_B (128 * ARS * 2)
#define AKV_B (64 * ARS * 2)
#define ATTN_SMEM (AQ_B + 4 * AKV_B)

__global__ void __launch_bounds__(ATH, 2)
attn_mma(const hf* __restrict__ Q, const hf* __restrict__ K,
         const hf* __restrict__ V, hf* __restrict__ O) {
    extern __shared__ __align__(128) char smem_raw[];
    uint32_t sQ = smem_u32(smem_raw);
    uint32_t sK = sQ + AQ_B;
    uint32_t sV = sQ + AQ_B + 2 * AKV_B;
    int qt = blockIdx.x, bh = blockIdx.y;
    int b = bh / N_HEAD, h = bh % N_HEAD;
    int tid = threadIdx.x, wid = tid >> 5, lane = tid & 31;
    int g = lane >> 2, t4 = lane & 3;
    int lq = lane >> 3, l7 = lane & 7;
    int aro = l7 + (lq & 1) * 8, ako = (lq >> 1) * 8;
    int bro = l7 + (lq >> 1) * 8, bko = (lq & 1) * 8;
    int tro = l7 + (lq & 1) * 8, tco = (lq >> 1) * 8;
    size_t hoff = (size_t)h * HDIM;

    for (int i = tid; i < 1024; i += ATH) {
        int row = i >> 3, c8 = i & 7;
        cp16(sQ + row * (ARS * 2) + c8 * 16,
             &Q[((size_t)(b * SEQ + qt * 128 + row)) * D_MOD + hoff + c8 * 8], 16);
    }
    asm volatile("cp.async.commit_group;" ::: "memory");

    int ktmax = 2 * qt + 1;

    auto pf = [&](int kt) {
        if (kt <= ktmax) {
            uint32_t kb = sK + (uint32_t)(kt & 1) * AKV_B;
            uint32_t vb = sV + (uint32_t)(kt & 1) * AKV_B;
#pragma unroll
            for (int i = 0; i < 2; ++i) {
                int g2 = tid + i * ATH;
                int row = g2 >> 3, c8 = g2 & 7;
                size_t goff = ((size_t)(b * SEQ + kt * 64 + row)) * D_MOD + hoff + c8 * 8;
                cp16(kb + row * (ARS * 2) + c8 * 16, &K[goff], 16);
                cp16(vb + row * (ARS * 2) + c8 * 16, &V[goff], 16);
            }
        }
        asm volatile("cp.async.commit_group;" ::: "memory");
    };

    float m0 = -1e30f, m1 = -1e30f, l0 = 0.f, l1 = 0.f;
    float o[8][4];
#pragma unroll
    for (int j = 0; j < 8; ++j)
#pragma unroll
        for (int k = 0; k < 4; ++k) o[j][k] = 0.f;

    int qrow0 = qt * 128 + wid * 16 + g;

    pf(0);
    for (int kt = 0; kt <= ktmax; ++kt) {
        pf(kt + 1);
        asm volatile("cp.async.wait_group 1;" ::: "memory");
        __syncthreads();
        uint32_t kb_ = sK + (uint32_t)(kt & 1) * AKV_B;
        uint32_t vb_ = sV + (uint32_t)(kt & 1) * AKV_B;

        float s[8][4];
#pragma unroll
        for (int j = 0; j < 8; ++j)
#pragma unroll
            for (int k = 0; k < 4; ++k) s[j][k] = 0.f;
#pragma unroll
        for (int kk = 0; kk < 4; ++kk) {
            int kbo = kk * 16;
            uint32_t aq[4];
            ldsm_x4(aq, sQ + (uint32_t)((wid * 16 + aro) * ARS + kbo + ako) * 2);
#pragma unroll
            for (int pr = 0; pr < 4; ++pr) {
                uint32_t r[4];
                ldsm_x4(r, kb_ + (uint32_t)((pr * 16 + bro) * ARS + kbo + bko) * 2);
                mma_f16(s[pr * 2], aq, r);
                mma_f16(s[pr * 2 + 1], aq, r + 2);
            }
        }

        float mx0 = -1e30f, mx1 = -1e30f;
#pragma unroll
        for (int j = 0; j < 8; ++j) {
            int col = kt * 64 + j * 8 + t4 * 2;
            s[j][0] = (col     <= qrow0)     ? s[j][0] * 0.125f : -1e30f;
            s[j][1] = (col + 1 <= qrow0)     ? s[j][1] * 0.125f : -1e30f;
            s[j][2] = (col     <= qrow0 + 8) ? s[j][2] * 0.125f : -1e30f;
            s[j][3] = (col + 1 <= qrow0 + 8) ? s[j][3] * 0.125f : -1e30f;
            mx0 = fmaxf(mx0, fmaxf(s[j][0], s[j][1]));
            mx1 = fmaxf(mx1, fmaxf(s[j][2], s[j][3]));
        }
        mx0 = fmaxf(mx0, __shfl_xor_sync(0xffffffffu, mx0, 1));
        mx0 = fmaxf(mx0, __shfl_xor_sync(0xffffffffu, mx0, 2));
        mx1 = fmaxf(mx1, __shfl_xor_sync(0xffffffffu, mx1, 1));
        mx1 = fmaxf(mx1, __shfl_xor_sync(0xffffffffu, mx1, 2));
        float mn0 = fmaxf(m0, mx0), mn1 = fmaxf(m1, mx1);
        float sc0 = __expf(m0 - mn0), sc1 = __expf(m1 - mn1);

        uint32_t plo[8], phi[8];
        float ps0 = 0.f, ps1 = 0.f;
#pragma unroll
        for (int j = 0; j < 8; ++j) {
            float p0 = __expf(s[j][0] - mn0);
            float p1 = __expf(s[j][1] - mn0);
            float p2 = __expf(s[j][2] - mn1);
            float p3 = __expf(s[j][3] - mn1);
            ps0 += p0 + p1; ps1 += p2 + p3;
            plo[j] = pack_h2(p0, p1);
            phi[j] = pack_h2(p2, p3);
        }
        ps0 += __shfl_xor_sync(0xffffffffu, ps0, 1);
        ps0 += __shfl_xor_sync(0xffffffffu, ps0, 2);
        ps1 += __shfl_xor_sync(0xffffffffu, ps1, 1);
        ps1 += __shfl_xor_sync(0xffffffffu, ps1, 2);
        l0 = l0 * sc0 + ps0;
        l1 = l1 * sc1 + ps1;
        m0 = mn0; m1 = mn1;
#pragma unroll
        for (int j = 0; j < 8; ++j) {
            o[j][0] *= sc0; o[j][1] *= sc0;
            o[j][2] *= sc1; o[j][3] *= sc1;
        }

#pragma unroll
        for (int t = 0; t < 4; ++t) {
            uint32_t ap[4] = {plo[2 * t], phi[2 * t], plo[2 * t + 1], phi[2 * t + 1]};
#pragma unroll
            for (int pr = 0; pr < 4; ++pr) {
                uint32_t r[4];
                ldsm_x4_t(r, vb_ + (uint32_t)((t * 16 + tro) * ARS + pr * 16 + tco) * 2);
                mma_f16(o[pr * 2], ap, r);
                mma_f16(o[pr * 2 + 1], ap, r + 2);
            }
        }
        __syncthreads();
    }

    float inv0 = 1.f / l0, inv1 = 1.f / l1;
    size_t r0 = ((size_t)(b * SEQ + qrow0)) * D_MOD + hoff;
    size_t r1 = r0 + 8 * D_MOD;
#pragma unroll
    for (int j = 0; j < 8; ++j) {
        int col = j * 8 + t4 * 2;
        *(uint32_t*)&O[r0 + col] = pack_h2(o[j][0] * inv0, o[j][1] * inv0);
        *(uint32_t*)&O[r1 + col] = pack_h2(o[j][2] * inv1, o[j][3] * inv1);
    }
}

// ---- router & bookkeeping ----
__global__ void zero_cnt_kernel() { if (threadIdx.x < NE) g_cnt[threadIdx.x] = 0; }
__global__ void init_entries_kernel() {
    int i = blockIdx.x * blockDim.x + threadIdx.x;
    if (i < ENT_CAP) g_entries[i] = -1;
}
__global__ void router_kernel(const float* __restrict__ h2, const float* __restrict__ Wr,
                              const float* __restrict__ rb) {
    int t = blockIdx.x;
    int w = threadIdx.x >> 5, lane = threadIdx.x & 31;
    __shared__ float sl[NE];
    if (w < NE) {
        const float* hr = h2 + (size_t)t * D_MOD;
        const float* wr = Wr + w * D_MOD;
        float s = 0.f;
        for (int c = lane; c < D_MOD; c += 32) s += hr[c] * wr[c];
        for (int o = 16; o; o >>= 1) s += __shfl_xor_sync(0xffffffffu, s, o);
        if (lane == 0) sl[w] = s + rb[w];
    }
    __syncthreads();
    if (threadIdx.x == 0) {
        float p[NE];
#pragma unroll
        for (int e = 0; e < NE; ++e) p[e] = 1.f / (1.f + expf(-sl[e]));
        int i0 = 0;
#pragma unroll
        for (int e = 1; e < NE; ++e) if (p[e] > p[i0]) i0 = e;
        int i1 = -1;
#pragma unroll
        for (int e = 0; e < NE; ++e) {
            if (e == i0) continue;
            if (i1 < 0 || p[e] > p[i1]) i1 = e;
        }
        float sum = p[i0] + p[i1];
        g_top[t * 2] = i0; g_top[t * 2 + 1] = i1;
        g_w[t * 2] = p[i0] / sum; g_w[t * 2 + 1] = p[i1] / sum;
        atomicAdd(&g_cnt[i0], 1);
        atomicAdd(&g_cnt[i1], 1);
    }
}
__global__ void offsets_kernel() {
    int off = 0;
    for (int e = 0; e < NE; ++e) {
        g_offs[e] = off;
        g_cursor[e] = off;
        off += ((g_cnt[e] + 127) >> 7) << 7;
    }
    g_offs[NE] = off;
}
__global__ void scatter_kernel() {
    int t = blockIdx.x * blockDim.x + threadIdx.x;
    if (t >= T_TOK) return;
#pragma unroll
    for (int slot = 0; slot < 2; ++slot) {
        int e = g_top[t * 2 + slot];
        int pos = atomicAdd(&g_cursor[e], 1);
        g_entries[pos] = t * 2 + slot;
    }
}
__global__ void combine_kernel(float* __restrict__ out) {
    int t = blockIdx.x;
    int tid = threadIdx.x;
    float w0 = g_w[t * 2], w1 = g_w[t * 2 + 1];
    size_t b0 = (size_t)(t * 2) * D_MOD, b1 = (size_t)(t * 2 + 1) * D_MOD, bt = (size_t)t * D_MOD;
#pragma unroll
    for (int u = 0; u < 3; ++u) {
        int c = tid + u * 192;
        out[bt + c] = g_x2[bt + c] + g_shared[bt + c] + w0 * g_rout[b0 + c] + w1 * g_rout[b1 + c];
    }
}

#define GETP(v, s) cudaGetSymbolAddress((void**)&v, s)

extern "C" void kernel_launch(void* const* d_in, const int* in_sizes, int n_in,
                              void* d_out, int out_size) {
    const float* x    = (const float*)d_in[0];
    const float* ln1w = (const float*)d_in[1];
    const float* ln2w = (const float*)d_in[2];
    const float* Wqd  = (const float*)d_in[3];
    const float* Wkvd = (const float*)d_in[4];
    const float* Wqu  = (const float*)d_in[5];
    const float* Wku  = (const float*)d_in[6];
    const float* Wvu  = (const float*)d_in[7];
    const float* Wo   = (const float*)d_in[8];
    const float* sg   = (const float*)d_in[9];
    const float* su   = (const float*)d_in[10];
    const float* sd   = (const float*)d_in[11];
    const float* rg   = (const float*)d_in[12];
    const float* ru   = (const float*)d_in[13];
    const float* rd   = (const float*)d_in[14];
    const float* Wr   = (const float*)d_in[15];
    const float* rb   = (const float*)d_in[16];
    float* out = (float*)d_out;

    float *px2, *ph2f, *pshared;
    GETP(px2, g_x2); GETP(ph2f, g_h2f); GETP(pshared, g_shared);
    hf *ph, *pql, *pkv, *paq, *pak, *pav, *po, *ph2, *pff, *pe;
    GETP(ph, a_h); GETP(pql, a_ql); GETP(pkv, a_kv);
    GETP(paq, a_q); GETP(pak, a_k); GETP(pav, a_v); GETP(po, a_o);
    GETP(ph2, a_h2); GETP(pff, a_ff); GETP(pe, a_e);
    hf *qdh, *qdl, *kdh, *kdl, *quh, *qul, *kuh, *kul, *vuh, *vul, *woh, *wol;
    hf *sgh, *sgl, *suh, *sul, *sdh, *sdl, *rgh, *rgl, *ruh, *rul, *rdh, *rdl;
    GETP(qdh, w_qdh); GETP(qdl, w_qdl); GETP(kdh, w_kdh); GETP(kdl, w_kdl);
    GETP(quh, w_quh); GETP(qul, w_qul); GETP(kuh, w_kuh); GETP(kul, w_kul);
    GETP(vuh, w_vuh); GETP(vul, w_vul); GETP(woh, w_oh); GETP(wol, w_ol);
    GETP(sgh, w_sgh); GETP(sgl, w_sgl); GETP(suh, w_suh); GETP(sul, w_sul);
    GETP(sdh, w_sdh); GETP(sdl, w_sdl); GETP(rgh, w_rgh); GETP(rgl, w_rgl);
    GETP(ruh, w_ruh); GETP(rul, w_rul); GETP(rdh, w_rdh); GETP(rdl, w_rdl);

    const int SMEM_G = NSTAGE * GSTAGE;   // 61440
    const int SMEM_D = NSTAGE * DSTAGE;   // 61440
    cudaFuncSetAttribute(gemm_mma<0>, cudaFuncAttributeMaxDynamicSharedMemorySize, SMEM_G);
    cudaFuncSetAttribute(gemm_mma<1>, cudaFuncAttributeMaxDynamicSharedMemorySize, SMEM_G);
    cudaFuncSetAttribute(gemm_mma<2>, cudaFuncAttributeMaxDynamicSharedMemorySize, SMEM_G);
    cudaFuncSetAttribute(gemm_mma<5>, cudaFuncAttributeMaxDynamicSharedMemorySize, SMEM_G);
    cudaFuncSetAttribute(dual_mma<0>, cudaFuncAttributeMaxDynamicSharedMemorySize, SMEM_D);
    cudaFuncSetAttribute(dual_mma<1>, cudaFuncAttributeMaxDynamicSharedMemorySize, SMEM_D);
    cudaFuncSetAttribute(dual_mma<2>, cudaFuncAttributeMaxDynamicSharedMemorySize, SMEM_D);
    cudaFuncSetAttribute(attn_mma, cudaFuncAttributeMaxDynamicSharedMemorySize, ATTN_SMEM);

    auto cvt = [&](const float* S, hf* H, hf* L, int R, int K, int Rp, int Kp) {
        long total8 = (long)Rp * Kp / 8;
        cvt_w8<<<(int)((total8 + 255) / 256), 256>>>(S, H, L, R, K, Kp, total8);
    };

    const int MB = T_TOK / 128;  // 64

    cvt(Wqd, qdh, qdl, 144, 576, 256, 576);
    cvt(Wkvd, kdh, kdl, 144, 576, 256, 576);
    rmsnorm_kernel<<<T_TOK, 192>>>(x, ln1w, nullptr, ph);
    dual_mma<0><<<dim3(6, MB), NTH, SMEM_D>>>(ph, qdh, qdl, kdh, kdl,
                                              pql, pkv, LATP, LAT, 18, 0);

    zero_cnt_kernel<<<1, 32>>>();
    init_entries_kernel<<<(ENT_CAP + 255) / 256, 256>>>();
    cvt(Wqu, quh, qul, 576, 144, 640, 192);
    cvt(Wku, kuh, kul, 576, 144, 640, 192);
    cvt(Wvu, vuh, vul, 576, 144, 640, 192);
    cvt(Wo, woh, wol, 576, 576, 640, 576);
    cvt(sg, sgh, sgl, 1536, 576, 1536, 576);
    cvt(su, suh, sul, 1536, 576, 1536, 576);
    cvt(sd, sdh, sdl, 576, 1536, 640, 1536);
    cvt(rg, rgh, rgl, NE * 1536, 576, NE * 1536, 576);
    cvt(ru, ruh, rul, NE * 1536, 576, NE * 1536, 576);
    for (int e = 0; e < NE; ++e)
        cvt(rd + (long)e * 576 * 1536, rdh + (long)e * 640 * 1536, rdl + (long)e * 640 * 1536,
            576, 1536, 640, 1536);

    gemm_mma<2><<<dim3(9, MB), NTH, SMEM_G>>>(pql, quh, qul, nullptr, nullptr,
                                              paq, D_MOD, D_MOD, 6, 0);
    dual_mma<0><<<dim3(18, MB), NTH, SMEM_D>>>(pkv, kuh, kul, vuh, vul,
                                               pak, pav, D_MOD, D_MOD, 6, 0);

    rope_kernel<<<T_TOK, 288>>>(paq, pak);

    attn_mma<<<dim3(SEQ / 128, 8 * N_HEAD), ATH, ATTN_SMEM>>>(paq, pak, pav, po);

    gemm_mma<1><<<dim3(9, MB), NTH, SMEM_G>>>(po, woh, wol, px2, x,
                                              nullptr, 0, D_MOD, 18, 0);

    rmsnorm_kernel<<<T_TOK, 192>>>(px2, ln2w, ph2f, ph2);

    dual_mma<1><<<dim3(FF / 32, MB), NTH, SMEM_D>>>(ph2, sgh, sgl, suh, sul,
                                                    pff, nullptr, FF, FF, 18, 0);
    gemm_mma<0><<<dim3(9, MB), NTH, SMEM_G>>>(pff, sdh, sdl, pshared, nullptr,
                                              nullptr, 0, D_MOD, 48, 0);

    router_kernel<<<T_TOK, 256>>>(ph2f, Wr, rb);
    offsets_kernel<<<1, 1>>>();
    scatter_kernel<<<T_TOK / 256, 256>>>();

    const int EB = ENT_CAP / 128;  // 135
    dual_mma<2><<<dim3(FF / 32, EB), NTH, SMEM_D>>>(ph2, rgh, rgl, ruh, rul,
                                                    pe, nullptr, FF, FF, 18,
                                                    (long)FF * D_MOD);
    gemm_mma<5><<<dim3(9, EB), NTH, SMEM_G>>>(pe, rdh, rdl, nullptr, nullptr,
                                              nullptr, 0, D_MOD, 48, (long)640 * FF);

    combine_kernel<<<T_TOK, 192>>>(out);
}

// round 16
// speedup vs baseline: 1.0328x; 1.0328x over previous
#include <cuda_runtime.h>
#include <cuda_fp16.h>
#include <math.h>
#include <stdint.h>

#define T_TOK 8192
#define D_MOD 576
#define N_HEAD 9
#define HDIM 64
#define LAT 144
#define LATP 192
#define FF 1536
#define NE 7
#define SEQ 1024
#define ENT_CAP 17280

typedef __half hf;

// ---------------- fp32 scratch ----------------
__device__ __align__(128) float g_x2[T_TOK * D_MOD];
__device__ __align__(128) float g_h2f[T_TOK * D_MOD];
__device__ __align__(128) float g_shared[T_TOK * D_MOD];
__device__ __align__(128) float g_rout[T_TOK * 2 * D_MOD];
__device__ float g_w[T_TOK * 2];
__device__ int   g_top[T_TOK * 2];
__device__ int   g_cnt[NE];
__device__ int   g_offs[NE + 1];
__device__ int   g_cursor[NE];
__device__ int   g_entries[ENT_CAP];

// ---------------- fp16 activations ----------------
__device__ __align__(128) hf a_h[T_TOK * D_MOD];
__device__ __align__(128) hf a_ql[T_TOK * LATP];
__device__ __align__(128) hf a_kv[T_TOK * LATP];
__device__ __align__(128) hf a_q[T_TOK * D_MOD];
__device__ __align__(128) hf a_k[T_TOK * D_MOD];
__device__ __align__(128) hf a_v[T_TOK * D_MOD];
__device__ __align__(128) hf a_o[T_TOK * D_MOD];
__device__ __align__(128) hf a_h2[T_TOK * D_MOD];
__device__ __align__(128) hf a_ff[T_TOK * FF];
__device__ __align__(128) hf a_e[ENT_CAP * FF];

// ---------------- fp16 hi/lo weights (row-padded) -------------------------
__device__ __align__(128) hf w_qdh[256 * 576];
__device__ __align__(128) hf w_qdl[256 * 576];
__device__ __align__(128) hf w_kdh[256 * 576];
__device__ __align__(128) hf w_kdl[256 * 576];
__device__ __align__(128) hf w_quh[640 * 192];
__device__ __align__(128) hf w_qul[640 * 192];
__device__ __align__(128) hf w_kuh[640 * 192];
__device__ __align__(128) hf w_kul[640 * 192];
__device__ __align__(128) hf w_vuh[640 * 192];
__device__ __align__(128) hf w_vul[640 * 192];
__device__ __align__(128) hf w_oh[640 * 576];
__device__ __align__(128) hf w_ol[640 * 576];
__device__ __align__(128) hf w_sgh[1536 * 576];
__device__ __align__(128) hf w_sgl[1536 * 576];
__device__ __align__(128) hf w_suh[1536 * 576];
__device__ __align__(128) hf w_sul[1536 * 576];
__device__ __align__(128) hf w_sdh[640 * 1536];
__device__ __align__(128) hf w_sdl[640 * 1536];
__device__ __align__(128) hf w_rgh[NE * 1536 * 576];
__device__ __align__(128) hf w_rgl[NE * 1536 * 576];
__device__ __align__(128) hf w_ruh[NE * 1536 * 576];
__device__ __align__(128) hf w_rul[NE * 1536 * 576];
__device__ __align__(128) hf w_rdh[NE * 640 * 1536];
__device__ __align__(128) hf w_rdl[NE * 640 * 1536];

// ---------------- helpers ----------------
__device__ __forceinline__ void cp16(uint32_t dst, const void* src, uint32_t sz) {
    asm volatile("cp.async.cg.shared.global [%0], [%1], 16, %2;" :: "r"(dst), "l"(src), "r"(sz) : "memory");
}
__device__ __forceinline__ uint32_t smem_u32(const void* p) {
    uint32_t a;
    asm("{ .reg .u64 t; cvta.to.shared.u64 t, %1; cvt.u32.u64 %0, t; }" : "=r"(a) : "l"(p));
    return a;
}
__device__ __forceinline__ void mma_f16(float* c, const uint32_t* a, const uint32_t* b) {
    asm volatile(
        "mma.sync.aligned.m16n8k16.row.col.f32.f16.f16.f32 "
        "{%0,%1,%2,%3}, {%4,%5,%6,%7}, {%8,%9}, {%0,%1,%2,%3};"
        : "+f"(c[0]), "+f"(c[1]), "+f"(c[2]), "+f"(c[3])
        : "r"(a[0]), "r"(a[1]), "r"(a[2]), "r"(a[3]), "r"(b[0]), "r"(b[1]));
}
__device__ __forceinline__ void ldsm_x4(uint32_t* r, uint32_t addr) {
    asm volatile("ldmatrix.sync.aligned.m8n8.x4.shared.b16 {%0,%1,%2,%3}, [%4];"
        : "=r"(r[0]), "=r"(r[1]), "=r"(r[2]), "=r"(r[3]) : "r"(addr));
}
__device__ __forceinline__ void ldsm_x4_t(uint32_t* r, uint32_t addr) {
    asm volatile("ldmatrix.sync.aligned.m8n8.x4.trans.shared.b16 {%0,%1,%2,%3}, [%4];"
        : "=r"(r[0]), "=r"(r[1]), "=r"(r[2]), "=r"(r[3]) : "r"(addr));
}
__device__ __forceinline__ uint32_t pack_h2(float a, float b) {
    __half2 h = __floats2half2_rn(a, b);
    return *(uint32_t*)&h;
}

#define NTH 256

// ======================= BIG-TILE family (R14): K-chunk 64, RS 72 ==========
#define RSB 72
#define BT_T (128 * RSB * 2)        // 18432
#define BG_STAGE (3 * BT_T)         // 55296 (A + Bh + Bl)
#define BD_B (64 * RSB * 2)         // 9216
#define BD_STAGE (BT_T + 4 * BD_B)  // 55296

// MODE: 0 fp32 | 5 MoE-down scatter fp32
template <int MODE>
__global__ void __launch_bounds__(NTH, 2)
gemm_big(const hf* __restrict__ AF,
         const hf* __restrict__ BH, const hf* __restrict__ BL,
         float* __restrict__ Cout,
         int N, int NC, long bstride) {
    extern __shared__ __align__(128) char smem_raw[];
    int tid = threadIdx.x, wid = tid >> 5, lane = tid & 31;
    int wm = wid >> 2, wn = wid & 3;
    int nBase = blockIdx.x * 128, mBase = blockIdx.y * 128;
    const int KP = NC * 64;

    __shared__ int s_tok[128];
    __shared__ int s_info[2];
    if (MODE == 5) {
        if (tid == 0) {
            int lim = g_offs[NE];
            if (mBase >= lim) s_info[1] = 0;
            else {
                int e = 0;
                while (mBase >= g_offs[e + 1]) ++e;
                s_info[0] = e; s_info[1] = 1;
            }
        }
        __syncthreads();
        if (!s_info[1]) return;
        if (tid < 128) s_tok[tid] = g_entries[mBase + tid];
        __syncthreads();
        long eo = (long)s_info[0] * bstride;
        BH += eo; BL += eo;
    }

    uint32_t sb = smem_u32(smem_raw);

    auto prefetch = [&](int c) {
        uint32_t base = sb + (uint32_t)(c & 1) * BG_STAGE;
        int k0 = c * 64;
#pragma unroll
        for (int i = 0; i < 4; ++i) {
            int g2 = tid + i * NTH;
            int row = g2 >> 3, c8 = g2 & 7;
            uint32_t dst = base + row * (RSB * 2) + c8 * 16;
            long aoff = (long)(mBase + row) * KP + k0 + c8 * 8;
            cp16(dst, AF + aoff, 16);
            long boff = (long)(nBase + row) * KP + k0 + c8 * 8;
            cp16(dst + BT_T, BH + boff, 16);
            cp16(dst + 2 * BT_T, BL + boff, 16);
        }
        asm volatile("cp.async.commit_group;" ::: "memory");
    };

    float acc[4][4][4];
#pragma unroll
    for (int i = 0; i < 4; ++i)
#pragma unroll
        for (int j = 0; j < 4; ++j)
#pragma unroll
            for (int k = 0; k < 4; ++k) acc[i][j][k] = 0.f;

    int g = lane >> 2, t4 = lane & 3;
    int lq = lane >> 3, l7 = lane & 7;
    int aro = l7 + (lq & 1) * 8, ako = (lq >> 1) * 8;
    int bro = l7 + (lq >> 1) * 8, bko = (lq & 1) * 8;

    prefetch(0);
    for (int c = 0; c < NC; ++c) {
        if (c + 1 < NC) {
            prefetch(c + 1);
            asm volatile("cp.async.wait_group 1;" ::: "memory");
        } else {
            asm volatile("cp.async.wait_group 0;" ::: "memory");
        }
        __syncthreads();

        uint32_t st = sb + (uint32_t)(c & 1) * BG_STAGE;
        uint32_t Af = st, Bh = st + BT_T, Bl = st + 2 * BT_T;

#pragma unroll
        for (int kk = 0; kk < 4; ++kk) {
            int kb = kk * 16;
            uint32_t bh[4][2], bl[4][2];
#pragma unroll
            for (int pr = 0; pr < 2; ++pr) {
                uint32_t r[4];
                uint32_t off = (uint32_t)((wn * 32 + pr * 16 + bro) * RSB + kb + bko) * 2;
                ldsm_x4(r, Bh + off);
                bh[pr * 2][0] = r[0]; bh[pr * 2][1] = r[1];
                bh[pr * 2 + 1][0] = r[2]; bh[pr * 2 + 1][1] = r[3];
                ldsm_x4(r, Bl + off);
                bl[pr * 2][0] = r[0]; bl[pr * 2][1] = r[1];
                bl[pr * 2 + 1][0] = r[2]; bl[pr * 2 + 1][1] = r[3];
            }
#pragma unroll
            for (int mp = 0; mp < 2; ++mp) {
                uint32_t ah0[4], ah1[4];
                uint32_t off0 = (uint32_t)((wm * 64 + (mp * 2) * 16 + aro) * RSB + kb + ako) * 2;
                uint32_t off1 = (uint32_t)((wm * 64 + (mp * 2 + 1) * 16 + aro) * RSB + kb + ako) * 2;
                ldsm_x4(ah0, Af + off0);
                ldsm_x4(ah1, Af + off1);
#pragma unroll
                for (int nt = 0; nt < 4; ++nt) mma_f16(acc[mp * 2][nt], ah0, bh[nt]);
#pragma unroll
                for (int nt = 0; nt < 4; ++nt) mma_f16(acc[mp * 2 + 1][nt], ah1, bh[nt]);
#pragma unroll
                for (int nt = 0; nt < 4; ++nt) mma_f16(acc[mp * 2][nt], ah0, bl[nt]);
#pragma unroll
                for (int nt = 0; nt < 4; ++nt) mma_f16(acc[mp * 2 + 1][nt], ah1, bl[nt]);
            }
        }
        __syncthreads();
    }

#pragma unroll
    for (int mt = 0; mt < 4; ++mt) {
#pragma unroll
        for (int nt = 0; nt < 4; ++nt) {
#pragma unroll
            for (int hh = 0; hh < 2; ++hh) {
                int lrow = wm * 64 + mt * 16 + g + hh * 8;
                int col = wn * 32 + nt * 8 + t4 * 2;
                float v0 = acc[mt][nt][hh * 2 + 0];
                float v1 = acc[mt][nt][hh * 2 + 1];
                long row = (long)(mBase + lrow);
                int c0 = nBase + col;
                if (MODE == 0) {
                    if (c0 < N) {
                        Cout[row * N + c0] = v0;
                        Cout[row * N + c0 + 1] = v1;
                    }
                } else {
                    int v = s_tok[lrow];
                    if (v >= 0 && c0 < N) {
                        long orow = (long)v * D_MOD;
                        g_rout[orow + c0] = v0;
                        g_rout[orow + c0 + 1] = v1;
                    }
                }
            }
        }
    }
}

// DM: 1 = dense swiglu -> fp16 OF1; 2 = MoE gather-A swiglu
template <int DM>
__global__ void __launch_bounds__(NTH, 2)
dual_big(const hf* __restrict__ AF,
         const hf* __restrict__ B1H, const hf* __restrict__ B1L,
         const hf* __restrict__ B2H, const hf* __restrict__ B2L,
         hf* __restrict__ OF1,
         int ldo, int NC, long bstride) {
    extern __shared__ __align__(128) char smem_raw[];
    int tid = threadIdx.x, wid = tid >> 5, lane = tid & 31;
    int wm = wid >> 1, wn = wid & 1;
    int nBase = blockIdx.x * 64, mBase = blockIdx.y * 128;
    const int KP = NC * 64;

    __shared__ int s_tok[128];
    __shared__ int s_info[2];
    if (DM == 2) {
        if (tid == 0) {
            int lim = g_offs[NE];
            if (mBase >= lim) s_info[1] = 0;
            else {
                int e = 0;
                while (mBase >= g_offs[e + 1]) ++e;
                s_info[0] = e; s_info[1] = 1;
            }
        }
        __syncthreads();
        if (!s_info[1]) return;
        if (tid < 128) s_tok[tid] = g_entries[mBase + tid];
        __syncthreads();
        long eo = (long)s_info[0] * bstride;
        B1H += eo; B1L += eo; B2H += eo; B2L += eo;
    }

    uint32_t sb = smem_u32(smem_raw);

    auto prefetch = [&](int c) {
        uint32_t base = sb + (uint32_t)(c & 1) * BD_STAGE;
        int k0 = c * 64;
#pragma unroll
        for (int i = 0; i < 4; ++i) {
            int g2 = tid + i * NTH;
            int row = g2 >> 3, c8 = g2 & 7;
            uint32_t dst = base + row * (RSB * 2) + c8 * 16;
            long aoff; uint32_t sz = 16;
            if (DM == 2) {
                int v = s_tok[row];
                if (v < 0) { sz = 0; aoff = 0; }
                else aoff = (long)(v >> 1) * KP + k0 + c8 * 8;
            } else {
                aoff = (long)(mBase + row) * KP + k0 + c8 * 8;
            }
            cp16(dst, AF + aoff, sz);
        }
#pragma unroll
        for (int i = 0; i < 2; ++i) {
            int g2 = tid + i * NTH;
            int row = g2 >> 3, c8 = g2 & 7;
            uint32_t dst = base + BT_T + row * (RSB * 2) + c8 * 16;
            long boff = (long)(nBase + row) * KP + k0 + c8 * 8;
            cp16(dst, B1H + boff, 16);
            cp16(dst + BD_B, B1L + boff, 16);
            cp16(dst + 2 * BD_B, B2H + boff, 16);
            cp16(dst + 3 * BD_B, B2L + boff, 16);
        }
        asm volatile("cp.async.commit_group;" ::: "memory");
    };

    float ac1[2][4][4], ac2[2][4][4];
#pragma unroll
    for (int i = 0; i < 2; ++i)
#pragma unroll
        for (int j = 0; j < 4; ++j)
#pragma unroll
            for (int k = 0; k < 4; ++k) { ac1[i][j][k] = 0.f; ac2[i][j][k] = 0.f; }

    int g = lane >> 2, t4 = lane & 3;
    int lq = lane >> 3, l7 = lane & 7;
    int aro = l7 + (lq & 1) * 8, ako = (lq >> 1) * 8;
    int bro = l7 + (lq >> 1) * 8, bko = (lq & 1) * 8;

    prefetch(0);
    for (int c = 0; c < NC; ++c) {
        if (c + 1 < NC) {
            prefetch(c + 1);
            asm volatile("cp.async.wait_group 1;" ::: "memory");
        } else {
            asm volatile("cp.async.wait_group 0;" ::: "memory");
        }
        __syncthreads();

        uint32_t st = sb + (uint32_t)(c & 1) * BD_STAGE;
        uint32_t Af = st, B1 = st + BT_T, B2 = B1 + 2 * BD_B;

#pragma unroll
        for (int kk = 0; kk < 4; ++kk) {
            int kb = kk * 16;
            uint32_t b1h[4][2], b1l[4][2], b2h[4][2], b2l[4][2];
#pragma unroll
            for (int pr = 0; pr < 2; ++pr) {
                uint32_t off = (uint32_t)((wn * 32 + pr * 16 + bro) * RSB + kb + bko) * 2;
                uint32_t r[4];
                ldsm_x4(r, B1 + off);
                b1h[pr * 2][0] = r[0]; b1h[pr * 2][1] = r[1];
                b1h[pr * 2 + 1][0] = r[2]; b1h[pr * 2 + 1][1] = r[3];
                ldsm_x4(r, B1 + BD_B + off);
                b1l[pr * 2][0] = r[0]; b1l[pr * 2][1] = r[1];
                b1l[pr * 2 + 1][0] = r[2]; b1l[pr * 2 + 1][1] = r[3];
                ldsm_x4(r, B2 + off);
                b2h[pr * 2][0] = r[0]; b2h[pr * 2][1] = r[1];
                b2h[pr * 2 + 1][0] = r[2]; b2h[pr * 2 + 1][1] = r[3];
                ldsm_x4(r, B2 + BD_B + off);
                b2l[pr * 2][0] = r[0]; b2l[pr * 2][1] = r[1];
                b2l[pr * 2 + 1][0] = r[2]; b2l[pr * 2 + 1][1] = r[3];
            }
#pragma unroll
            for (int mt = 0; mt < 2; ++mt) {
                uint32_t ah[4];
                uint32_t off = (uint32_t)((wm * 32 + mt * 16 + aro) * RSB + kb + ako) * 2;
                ldsm_x4(ah, Af + off);
#pragma unroll
                for (int nt = 0; nt < 4; ++nt) mma_f16(ac1[mt][nt], ah, b1h[nt]);
#pragma unroll
                for (int nt = 0; nt < 4; ++nt) mma_f16(ac2[mt][nt], ah, b2h[nt]);
#pragma unroll
                for (int nt = 0; nt < 4; ++nt) mma_f16(ac1[mt][nt], ah, b1l[nt]);
#pragma unroll
                for (int nt = 0; nt < 4; ++nt) mma_f16(ac2[mt][nt], ah, b2l[nt]);
            }
        }
        __syncthreads();
    }

#pragma unroll
    for (int mt = 0; mt < 2; ++mt) {
#pragma unroll
        for (int nt = 0; nt < 4; ++nt) {
#pragma unroll
            for (int hh = 0; hh < 2; ++hh) {
                int lrow = wm * 32 + mt * 16 + g + hh * 8;
                int col = wn * 32 + nt * 8 + t4 * 2;
                float u0 = ac1[mt][nt][hh * 2 + 0];
                float u1 = ac1[mt][nt][hh * 2 + 1];
                float v0 = ac2[mt][nt][hh * 2 + 0];
                float v1 = ac2[mt][nt][hh * 2 + 1];
                long row = (long)(mBase + lrow);
                int c0 = nBase + col;
                float o0 = (u0 / (1.f + __expf(-u0))) * v0;
                float o1 = (u1 / (1.f + __expf(-u1))) * v1;
                long orow = row * ldo;
                OF1[orow + c0]     = __float2half_rn(o0);
                OF1[orow + c0 + 1] = __float2half_rn(o1);
            }
        }
    }
}

// ======================= SMALL-TILE family (R15): K-chunk 32, RS 40 ========
#define RSS 40
#define ST_A (128 * RSS * 2)          // 10240
#define ST_B (64 * RSS * 2)           // 5120
#define SG_STAGE (ST_A + 2 * ST_B)    // 20480
#define SD_B (32 * RSS * 2)           // 2560
#define SD_STAGE (ST_A + 4 * SD_B)    // 20480
#define NST 3

// MODE: 1 fp32+Res | 2 fp16 out (zero-pad to ldo)
template <int MODE>
__global__ void __launch_bounds__(NTH, 3)
gemm_sm(const hf* __restrict__ AF,
        const hf* __restrict__ BH, const hf* __restrict__ BL,
        float* __restrict__ Cout, const float* __restrict__ Res,
        hf* __restrict__ OF,
        int ldo, int N, int NC) {
    extern __shared__ __align__(128) char smem_raw[];
    int tid = threadIdx.x, wid = tid >> 5, lane = tid & 31;
    int wm = wid >> 1, wn = wid & 1;
    int nBase = blockIdx.x * 64, mBase = blockIdx.y * 128;
    const int KP = NC * 32;

    uint32_t sb = smem_u32(smem_raw);

    auto prefetch = [&](int c) {
        if (c < NC) {
            uint32_t base = sb + (uint32_t)(c % NST) * SG_STAGE;
            int k0 = c * 32;
#pragma unroll
            for (int i = 0; i < 2; ++i) {
                int g2 = tid + i * NTH;
                int row = g2 >> 2, c4 = g2 & 3;
                uint32_t dst = base + row * (RSS * 2) + c4 * 16;
                long aoff = (long)(mBase + row) * KP + k0 + c4 * 8;
                cp16(dst, AF + aoff, 16);
            }
            {
                int row = tid >> 2, c4 = tid & 3;
                uint32_t dst = base + ST_A + row * (RSS * 2) + c4 * 16;
                long boff = (long)(nBase + row) * KP + k0 + c4 * 8;
                cp16(dst, BH + boff, 16);
                cp16(dst + ST_B, BL + boff, 16);
            }
        }
        asm volatile("cp.async.commit_group;" ::: "memory");
    };

    float acc[2][4][4];
#pragma unroll
    for (int i = 0; i < 2; ++i)
#pragma unroll
        for (int j = 0; j < 4; ++j)
#pragma unroll
            for (int k = 0; k < 4; ++k) acc[i][j][k] = 0.f;

    int g = lane >> 2, t4 = lane & 3;
    int lq = lane >> 3, l7 = lane & 7;
    int aro = l7 + (lq & 1) * 8, ako = (lq >> 1) * 8;
    int bro = l7 + (lq >> 1) * 8, bko = (lq & 1) * 8;

    prefetch(0);
    prefetch(1);
    prefetch(2);
    for (int c = 0; c < NC; ++c) {
        asm volatile("cp.async.wait_group %0;" :: "n"(NST - 1) : "memory");
        __syncthreads();
        uint32_t st = sb + (uint32_t)(c % NST) * SG_STAGE;
        uint32_t Af = st, Bh = st + ST_A, Bl = Bh + ST_B;

#pragma unroll
        for (int kk = 0; kk < 2; ++kk) {
            int kb = kk * 16;
            uint32_t bh[4][2], bl[4][2];
#pragma unroll
            for (int pr = 0; pr < 2; ++pr) {
                uint32_t r[4];
                uint32_t off = (uint32_t)((wn * 32 + pr * 16 + bro) * RSS + kb + bko) * 2;
                ldsm_x4(r, Bh + off);
                bh[pr * 2][0] = r[0]; bh[pr * 2][1] = r[1];
                bh[pr * 2 + 1][0] = r[2]; bh[pr * 2 + 1][1] = r[3];
                ldsm_x4(r, Bl + off);
                bl[pr * 2][0] = r[0]; bl[pr * 2][1] = r[1];
                bl[pr * 2 + 1][0] = r[2]; bl[pr * 2 + 1][1] = r[3];
            }
            uint32_t ah0[4], ah1[4];
            uint32_t off0 = (uint32_t)((wm * 32 + aro) * RSS + kb + ako) * 2;
            uint32_t off1 = (uint32_t)((wm * 32 + 16 + aro) * RSS + kb + ako) * 2;
            ldsm_x4(ah0, Af + off0);
            ldsm_x4(ah1, Af + off1);
#pragma unroll
            for (int nt = 0; nt < 4; ++nt) mma_f16(acc[0][nt], ah0, bh[nt]);
#pragma unroll
            for (int nt = 0; nt < 4; ++nt) mma_f16(acc[1][nt], ah1, bh[nt]);
#pragma unroll
            for (int nt = 0; nt < 4; ++nt) mma_f16(acc[0][nt], ah0, bl[nt]);
#pragma unroll
            for (int nt = 0; nt < 4; ++nt) mma_f16(acc[1][nt], ah1, bl[nt]);
        }
        __syncthreads();
        prefetch(c + NST);
    }

#pragma unroll
    for (int mt = 0; mt < 2; ++mt) {
#pragma unroll
        for (int nt = 0; nt < 4; ++nt) {
#pragma unroll
            for (int hh = 0; hh < 2; ++hh) {
                int lrow = wm * 32 + mt * 16 + g + hh * 8;
                int col = wn * 32 + nt * 8 + t4 * 2;
                float v0 = acc[mt][nt][hh * 2 + 0];
                float v1 = acc[mt][nt][hh * 2 + 1];
                long row = (long)(mBase + lrow);
                int c0 = nBase + col;
                if (MODE == 1) {
                    if (c0 < N) {
                        Cout[row * N + c0]     = v0 + Res[row * N + c0];
                        Cout[row * N + c0 + 1] = v1 + Res[row * N + c0 + 1];
                    }
                } else {
                    if (c0 < ldo) {
                        long orow = row * ldo;
                        OF[orow + c0]     = __float2half_rn((c0 < N) ? v0 : 0.f);
                        OF[orow + c0 + 1] = __float2half_rn((c0 + 1 < N) ? v1 : 0.f);
                    }
                }
            }
        }
    }
}

// DM 0: two fp16 outputs (zero-pad to ldo)
__global__ void __launch_bounds__(NTH, 3)
dual_sm(const hf* __restrict__ AF,
        const hf* __restrict__ B1H, const hf* __restrict__ B1L,
        const hf* __restrict__ B2H, const hf* __restrict__ B2L,
        hf* __restrict__ OF1, hf* __restrict__ OF2,
        int ldo, int N, int NC) {
    extern __shared__ __align__(128) char smem_raw[];
    int tid = threadIdx.x, wid = tid >> 5, lane = tid & 31;
    int wm = wid >> 1, wn = wid & 1;
    int nBase = blockIdx.x * 32, mBase = blockIdx.y * 128;
    const int KP = NC * 32;

    uint32_t sb = smem_u32(smem_raw);

    auto prefetch = [&](int c) {
        if (c < NC) {
            uint32_t base = sb + (uint32_t)(c % NST) * SD_STAGE;
            int k0 = c * 32;
#pragma unroll
            for (int i = 0; i < 2; ++i) {
                int g2 = tid + i * NTH;
                int row = g2 >> 2, c4 = g2 & 3;
                uint32_t dst = base + row * (RSS * 2) + c4 * 16;
                long aoff = (long)(mBase + row) * KP + k0 + c4 * 8;
                cp16(dst, AF + aoff, 16);
            }
#pragma unroll
            for (int i = 0; i < 2; ++i) {
                int idx = tid + i * NTH;
                int m = idx >> 7, rem = idx & 127;
                int row = rem >> 2, c4 = rem & 3;
                const hf* bp = (m == 0) ? B1H : (m == 1) ? B1L : (m == 2) ? B2H : B2L;
                uint32_t dst = base + ST_A + (uint32_t)m * SD_B + row * (RSS * 2) + c4 * 16;
                long boff = (long)(nBase + row) * KP + k0 + c4 * 8;
                cp16(dst, bp + boff, 16);
            }
        }
        asm volatile("cp.async.commit_group;" ::: "memory");
    };

    float ac1[2][2][4], ac2[2][2][4];
#pragma unroll
    for (int i = 0; i < 2; ++i)
#pragma unroll
        for (int j = 0; j < 2; ++j)
#pragma unroll
            for (int k = 0; k < 4; ++k) { ac1[i][j][k] = 0.f; ac2[i][j][k] = 0.f; }

    int g = lane >> 2, t4 = lane & 3;
    int lq = lane >> 3, l7 = lane & 7;
    int aro = l7 + (lq & 1) * 8, ako = (lq >> 1) * 8;
    int bro = l7 + (lq >> 1) * 8, bko = (lq & 1) * 8;

    prefetch(0);
    prefetch(1);
    prefetch(2);
    for (int c = 0; c < NC; ++c) {
        asm volatile("cp.async.wait_group %0;" :: "n"(NST - 1) : "memory");
        __syncthreads();
        uint32_t st = sb + (uint32_t)(c % NST) * SD_STAGE;
        uint32_t Af = st;
        uint32_t B1 = st + ST_A, B2 = B1 + 2 * SD_B;

#pragma unroll
        for (int kk = 0; kk < 2; ++kk) {
            int kb = kk * 16;
            uint32_t b1h[2][2], b1l[2][2], b2h[2][2], b2l[2][2];
            {
                uint32_t off = (uint32_t)((wn * 16 + bro) * RSS + kb + bko) * 2;
                uint32_t r[4];
                ldsm_x4(r, B1 + off);
                b1h[0][0] = r[0]; b1h[0][1] = r[1]; b1h[1][0] = r[2]; b1h[1][1] = r[3];
                ldsm_x4(r, B1 + SD_B + off);
                b1l[0][0] = r[0]; b1l[0][1] = r[1]; b1l[1][0] = r[2]; b1l[1][1] = r[3];
                ldsm_x4(r, B2 + off);
                b2h[0][0] = r[0]; b2h[0][1] = r[1]; b2h[1][0] = r[2]; b2h[1][1] = r[3];
                ldsm_x4(r, B2 + SD_B + off);
                b2l[0][0] = r[0]; b2l[0][1] = r[1]; b2l[1][0] = r[2]; b2l[1][1] = r[3];
            }
#pragma unroll
            for (int mt = 0; mt < 2; ++mt) {
                uint32_t ah[4];
                uint32_t off = (uint32_t)((wm * 32 + mt * 16 + aro) * RSS + kb + ako) * 2;
                ldsm_x4(ah, Af + off);
#pragma unroll
                for (int nt = 0; nt < 2; ++nt) mma_f16(ac1[mt][nt], ah, b1h[nt]);
#pragma unroll
                for (int nt = 0; nt < 2; ++nt) mma_f16(ac2[mt][nt], ah, b2h[nt]);
#pragma unroll
                for (int nt = 0; nt < 2; ++nt) mma_f16(ac1[mt][nt], ah, b1l[nt]);
#pragma unroll
                for (int nt = 0; nt < 2; ++nt) mma_f16(ac2[mt][nt], ah, b2l[nt]);
            }
        }
        __syncthreads();
        prefetch(c + NST);
    }

#pragma unroll
    for (int mt = 0; mt < 2; ++mt) {
#pragma unroll
        for (int nt = 0; nt < 2; ++nt) {
#pragma unroll
            for (int hh = 0; hh < 2; ++hh) {
                int lrow = wm * 32 + mt * 16 + g + hh * 8;
                int col = wn * 16 + nt * 8 + t4 * 2;
                float u0 = ac1[mt][nt][hh * 2 + 0];
                float u1 = ac1[mt][nt][hh * 2 + 1];
                float v0 = ac2[mt][nt][hh * 2 + 0];
                float v1 = ac2[mt][nt][hh * 2 + 1];
                long row = (long)(mBase + lrow);
                int c0 = nBase + col;
                if (c0 < ldo) {
                    long orow = row * ldo;
                    OF1[orow + c0]     = __float2half_rn((c0 < N) ? u0 : 0.f);
                    OF1[orow + c0 + 1] = __float2half_rn((c0 + 1 < N) ? u1 : 0.f);
                    OF2[orow + c0]     = __float2half_rn((c0 < N) ? v0 : 0.f);
                    OF2[orow + c0 + 1] = __float2half_rn((c0 + 1 < N) ? v1 : 0.f);
                }
            }
        }
    }
}

// ---- fast fp32 -> padded fp16 hi/lo: 8 elems/thread ----
__global__ void cvt_w8(const float* __restrict__ S, hf* __restrict__ H,
                       hf* __restrict__ L, int R, int K, int Kp, long total8) {
    long i = (long)blockIdx.x * blockDim.x + threadIdx.x;
    if (i >= total8) return;
    long i8 = i * 8;
    int r = (int)(i8 / Kp), c = (int)(i8 % Kp);
    uint4 ho, lo;
    if (r < R && c < K) {
        const float* src = S + (long)r * K + c;
        float4 v0 = *(const float4*)src;
        float4 v1 = *(const float4*)(src + 4);
        float vv[8] = {v0.x, v0.y, v0.z, v0.w, v1.x, v1.y, v1.z, v1.w};
        hf hh_[8], ll_[8];
#pragma unroll
        for (int j = 0; j < 8; ++j) {
            hf h = __float2half_rn(vv[j]);
            hh_[j] = h;
            ll_[j] = __float2half_rn(vv[j] - __half2float(h));
        }
        ho = *(uint4*)hh_;
        lo = *(uint4*)ll_;
    } else {
        ho = make_uint4(0, 0, 0, 0);
        lo = ho;
    }
    *(uint4*)(H + i8) = ho;
    *(uint4*)(L + i8) = lo;
}

// ---- rmsnorm ----
__global__ void rmsnorm_kernel(const float* __restrict__ x, const float* __restrict__ w,
                               float* __restrict__ outf, hf* __restrict__ outh) {
    int t = blockIdx.x;
    int tid = threadIdx.x;
    const float* xr = x + (size_t)t * D_MOD;
    float v0 = xr[tid], v1 = xr[tid + 192], v2 = xr[tid + 384];
    float ss = v0 * v0 + v1 * v1 + v2 * v2;
    for (int o = 16; o; o >>= 1) ss += __shfl_xor_sync(0xffffffffu, ss, o);
    __shared__ float red[8];
    int wid = tid >> 5, lane = tid & 31;
    if (lane == 0) red[wid] = ss;
    __syncthreads();
    if (tid == 0) {
        float s = 0.f;
        for (int i = 0; i < 6; ++i) s += red[i];
        red[0] = rsqrtf(s / (float)D_MOD + 1e-5f);
    }
    __syncthreads();
    float r = red[0];
    size_t bt = (size_t)t * D_MOD;
    float vv[3] = {v0, v1, v2};
#pragma unroll
    for (int u = 0; u < 3; ++u) {
        int c = tid + u * 192;
        float v = vv[u] * r * w[c];
        if (outf) outf[bt + c] = v;
        outh[bt + c] = __float2half_rn(v);
    }
}

// ---- RoPE: in-place on fp16 q/k ----
__global__ void rope_kernel(hf* __restrict__ q, hf* __restrict__ k) {
    int t = blockIdx.x;
    int tid = threadIdx.x;
    int h = tid >> 5, i = tid & 31;
    int pos = t & (SEQ - 1);
    float inv = __expf(-(float)i * 0.28782313662425572f);
    float f = (float)pos * inv;
    float sv, cv;
    sincosf(f, &sv, &cv);
    size_t base = (size_t)t * D_MOD + h * HDIM + i;
    float q1 = __half2float(q[base]), q2 = __half2float(q[base + 32]);
    q[base]      = __float2half_rn(q1 * cv - q2 * sv);
    q[base + 32] = __float2half_rn(q2 * cv + q1 * sv);
    float k1 = __half2float(k[base]), k2 = __half2float(k[base + 32]);
    k[base]      = __float2half_rn(k1 * cv - k2 * sv);
    k[base + 32] = __float2half_rn(k2 * cv + k1 * sv);
}

// ---- flash attention (ARS=72) ----
#define ARS 72
#define ATH 256
#define AQ_B (128 * ARS * 2)
#define AKV_B (64 * ARS * 2)
#define ATTN_SMEM (AQ_B + 4 * AKV_B)

__global__ void __launch_bounds__(ATH, 2)
attn_mma(const hf* __restrict__ Q, const hf* __restrict__ K,
         const hf* __restrict__ V, hf* __restrict__ O) {
    extern __shared__ __align__(128) char smem_raw[];
    uint32_t sQ = smem_u32(smem_raw);
    uint32_t sK = sQ + AQ_B;
    uint32_t sV = sQ + AQ_B + 2 * AKV_B;
    int qt = blockIdx.x, bh = blockIdx.y;
    int b = bh / N_HEAD, h = bh % N_HEAD;
    int tid = threadIdx.x, wid = tid >> 5, lane = tid & 31;
    int g = lane >> 2, t4 = lane & 3;
    int lq = lane >> 3, l7 = lane & 7;
    int aro = l7 + (lq & 1) * 8, ako = (lq >> 1) * 8;
    int bro = l7 + (lq >> 1) * 8, bko = (lq & 1) * 8;
    int tro = l7 + (lq & 1) * 8, tco = (lq >> 1) * 8;
    size_t hoff = (size_t)h * HDIM;

    for (int i = tid; i < 1024; i += ATH) {
        int row = i >> 3, c8 = i & 7;
        cp16(sQ + row * (ARS * 2) + c8 * 16,
             &Q[((size_t)(b * SEQ + qt * 128 + row)) * D_MOD + hoff + c8 * 8], 16);
    }
    asm volatile("cp.async.commit_group;" ::: "memory");

    int ktmax = 2 * qt + 1;

    auto pf = [&](int kt) {
        if (kt <= ktmax) {
            uint32_t kb = sK + (uint32_t)(kt & 1) * AKV_B;
            uint32_t vb = sV + (uint32_t)(kt & 1) * AKV_B;
#pragma unroll
            for (int i = 0; i < 2; ++i) {
                int g2 = tid + i * ATH;
                int row = g2 >> 3, c8 = g2 & 7;
                size_t goff = ((size_t)(b * SEQ + kt * 64 + row)) * D_MOD + hoff + c8 * 8;
                cp16(kb + row * (ARS * 2) + c8 * 16, &K[goff], 16);
                cp16(vb + row * (ARS * 2) + c8 * 16, &V[goff], 16);
            }
        }
        asm volatile("cp.async.commit_group;" ::: "memory");
    };

    float m0 = -1e30f, m1 = -1e30f, l0 = 0.f, l1 = 0.f;
    float o[8][4];
#pragma unroll
    for (int j = 0; j < 8; ++j)
#pragma unroll
        for (int k = 0; k < 4; ++k) o[j][k] = 0.f;

    int qrow0 = qt * 128 + wid * 16 + g;

    pf(0);
    for (int kt = 0; kt <= ktmax; ++kt) {
        pf(kt + 1);
        asm volatile("cp.async.wait_group 1;" ::: "memory");
        __syncthreads();
        uint32_t kb_ = sK + (uint32_t)(kt & 1) * AKV_B;
        uint32_t vb_ = sV + (uint32_t)(kt & 1) * AKV_B;

        float s[8][4];
#pragma unroll
        for (int j = 0; j < 8; ++j)
#pragma unroll
            for (int k = 0; k < 4; ++k) s[j][k] = 0.f;
#pragma unroll
        for (int kk = 0; kk < 4; ++kk) {
            int kbo = kk * 16;
            uint32_t aq[4];
            ldsm_x4(aq, sQ + (uint32_t)((wid * 16 + aro) * ARS + kbo + ako) * 2);
#pragma unroll
            for (int pr = 0; pr < 4; ++pr) {
                uint32_t r[4];
                ldsm_x4(r, kb_ + (uint32_t)((pr * 16 + bro) * ARS + kbo + bko) * 2);
                mma_f16(s[pr * 2], aq, r);
                mma_f16(s[pr * 2 + 1], aq, r + 2);
            }
        }

        float mx0 = -1e30f, mx1 = -1e30f;
#pragma unroll
        for (int j = 0; j < 8; ++j) {
            int col = kt * 64 + j * 8 + t4 * 2;
            s[j][0] = (col     <= qrow0)     ? s[j][0] * 0.125f : -1e30f;
            s[j][1] = (col + 1 <= qrow0)     ? s[j][1] * 0.125f : -1e30f;
            s[j][2] = (col     <= qrow0 + 8) ? s[j][2] * 0.125f : -1e30f;
            s[j][3] = (col + 1 <= qrow0 + 8) ? s[j][3] * 0.125f : -1e30f;
            mx0 = fmaxf(mx0, fmaxf(s[j][0], s[j][1]));
            mx1 = fmaxf(mx1, fmaxf(s[j][2], s[j][3]));
        }
        mx0 = fmaxf(mx0, __shfl_xor_sync(0xffffffffu, mx0, 1));
        mx0 = fmaxf(mx0, __shfl_xor_sync(0xffffffffu, mx0, 2));
        mx1 = fmaxf(mx1, __shfl_xor_sync(0xffffffffu, mx1, 1));
        mx1 = fmaxf(mx1, __shfl_xor_sync(0xffffffffu, mx1, 2));
        float mn0 = fmaxf(m0, mx0), mn1 = fmaxf(m1, mx1);
        float sc0 = __expf(m0 - mn0), sc1 = __expf(m1 - mn1);

        uint32_t plo[8], phi[8];
        float ps0 = 0.f, ps1 = 0.f;
#pragma unroll
        for (int j = 0; j < 8; ++j) {
            float p0 = __expf(s[j][0] - mn0);
            float p1 = __expf(s[j][1] - mn0);
            float p2 = __expf(s[j][2] - mn1);
            float p3 = __expf(s[j][3] - mn1);
            ps0 += p0 + p1; ps1 += p2 + p3;
            plo[j] = pack_h2(p0, p1);
            phi[j] = pack_h2(p2, p3);
        }
        ps0 += __shfl_xor_sync(0xffffffffu, ps0, 1);
        ps0 += __shfl_xor_sync(0xffffffffu, ps0, 2);
        ps1 += __shfl_xor_sync(0xffffffffu, ps1, 1);
        ps1 += __shfl_xor_sync(0xffffffffu, ps1, 2);
        l0 = l0 * sc0 + ps0;
        l1 = l1 * sc1 + ps1;
        m0 = mn0; m1 = mn1;
#pragma unroll
        for (int j = 0; j < 8; ++j) {
            o[j][0] *= sc0; o[j][1] *= sc0;
            o[j][2] *= sc1; o[j][3] *= sc1;
        }

#pragma unroll
        for (int t = 0; t < 4; ++t) {
            uint32_t ap[4] = {plo[2 * t], phi[2 * t], plo[2 * t + 1], phi[2 * t + 1]};
#pragma unroll
            for (int pr = 0; pr < 4; ++pr) {
                uint32_t r[4];
                ldsm_x4_t(r, vb_ + (uint32_t)((t * 16 + tro) * ARS + pr * 16 + tco) * 2);
                mma_f16(o[pr * 2], ap, r);
                mma_f16(o[pr * 2 + 1], ap, r + 2);
            }
        }
        __syncthreads();
    }

    float inv0 = 1.f / l0, inv1 = 1.f / l1;
    size_t r0 = ((size_t)(b * SEQ + qrow0)) * D_MOD + hoff;
    size_t r1 = r0 + 8 * D_MOD;
#pragma unroll
    for (int j = 0; j < 8; ++j) {
        int col = j * 8 + t4 * 2;
        *(uint32_t*)&O[r0 + col] = pack_h2(o[j][0] * inv0, o[j][1] * inv0);
        *(uint32_t*)&O[r1 + col] = pack_h2(o[j][2] * inv1, o[j][3] * inv1);
    }
}

// ---- router & bookkeeping ----
__global__ void zero_cnt_kernel() { if (threadIdx.x < NE) g_cnt[threadIdx.x] = 0; }
__global__ void init_entries_kernel() {
    int i = blockIdx.x * blockDim.x + threadIdx.x;
    if (i < ENT_CAP) g_entries[i] = -1;
}
__global__ void router_kernel(const float* __restrict__ h2, const float* __restrict__ Wr,
                              const float* __restrict__ rb) {
    int t = blockIdx.x;
    int w = threadIdx.x >> 5, lane = threadIdx.x & 31;
    __shared__ float sl[NE];
    if (w < NE) {
        const float* hr = h2 + (size_t)t * D_MOD;
        const float* wr = Wr + w * D_MOD;
        float s = 0.f;
        for (int c = lane; c < D_MOD; c += 32) s += hr[c] * wr[c];
        for (int o = 16; o; o >>= 1) s += __shfl_xor_sync(0xffffffffu, s, o);
        if (lane == 0) sl[w] = s + rb[w];
    }
    __syncthreads();
    if (threadIdx.x == 0) {
        float p[NE];
#pragma unroll
        for (int e = 0; e < NE; ++e) p[e] = 1.f / (1.f + expf(-sl[e]));
        int i0 = 0;
#pragma unroll
        for (int e = 1; e < NE; ++e) if (p[e] > p[i0]) i0 = e;
        int i1 = -1;
#pragma unroll
        for (int e = 0; e < NE; ++e) {
            if (e == i0) continue;
            if (i1 < 0 || p[e] > p[i1]) i1 = e;
        }
        float sum = p[i0] + p[i1];
        g_top[t * 2] = i0; g_top[t * 2 + 1] = i1;
        g_w[t * 2] = p[i0] / sum; g_w[t * 2 + 1] = p[i1] / sum;
        atomicAdd(&g_cnt[i0], 1);
        atomicAdd(&g_cnt[i1], 1);
    }
}
__global__ void offsets_kernel() {
    int off = 0;
    for (int e = 0; e < NE; ++e) {
        g_offs[e] = off;
        g_cursor[e] = off;
        off += ((g_cnt[e] + 127) >> 7) << 7;
    }
    g_offs[NE] = off;
}
__global__ void scatter_kernel() {
    int t = blockIdx.x * blockDim.x + threadIdx.x;
    if (t >= T_TOK) return;
#pragma unroll
    for (int slot = 0; slot < 2; ++slot) {
        int e = g_top[t * 2 + slot];
        int pos = atomicAdd(&g_cursor[e], 1);
        g_entries[pos] = t * 2 + slot;
    }
}
__global__ void combine_kernel(float* __restrict__ out) {
    int t = blockIdx.x;
    int tid = threadIdx.x;
    float w0 = g_w[t * 2], w1 = g_w[t * 2 + 1];
    size_t b0 = (size_t)(t * 2) * D_MOD, b1 = (size_t)(t * 2 + 1) * D_MOD, bt = (size_t)t * D_MOD;
#pragma unroll
    for (int u = 0; u < 3; ++u) {
        int c = tid + u * 192;
        out[bt + c] = g_x2[bt + c] + g_shared[bt + c] + w0 * g_rout[b0 + c] + w1 * g_rout[b1 + c];
    }
}

#define GETP(v, s) cudaGetSymbolAddress((void**)&v, s)

extern "C" void kernel_launch(void* const* d_in, const int* in_sizes, int n_in,
                              void* d_out, int out_size) {
    const float* x    = (const float*)d_in[0];
    const float* ln1w = (const float*)d_in[1];
    const float* ln2w = (const float*)d_in[2];
    const float* Wqd  = (const float*)d_in[3];
    const float* Wkvd = (const float*)d_in[4];
    const float* Wqu  = (const float*)d_in[5];
    const float* Wku  = (const float*)d_in[6];
    const float* Wvu  = (const float*)d_in[7];
    const float* Wo   = (const float*)d_in[8];
    const float* sg   = (const float*)d_in[9];
    const float* su   = (const float*)d_in[10];
    const float* sd   = (const float*)d_in[11];
    const float* rg   = (const float*)d_in[12];
    const float* ru   = (const float*)d_in[13];
    const float* rd   = (const float*)d_in[14];
    const float* Wr   = (const float*)d_in[15];
    const float* rb   = (const float*)d_in[16];
    float* out = (float*)d_out;

    float *px2, *ph2f, *pshared;
    GETP(px2, g_x2); GETP(ph2f, g_h2f); GETP(pshared, g_shared);
    hf *ph, *pql, *pkv, *paq, *pak, *pav, *po, *ph2, *pff, *pe;
    GETP(ph, a_h); GETP(pql, a_ql); GETP(pkv, a_kv);
    GETP(paq, a_q); GETP(pak, a_k); GETP(pav, a_v); GETP(po, a_o);
    GETP(ph2, a_h2); GETP(pff, a_ff); GETP(pe, a_e);
    hf *qdh, *qdl, *kdh, *kdl, *quh, *qul, *kuh, *kul, *vuh, *vul, *woh, *wol;
    hf *sgh, *sgl, *suh, *sul, *sdh, *sdl, *rgh, *rgl, *ruh, *rul, *rdh, *rdl;
    GETP(qdh, w_qdh); GETP(qdl, w_qdl); GETP(kdh, w_kdh); GETP(kdl, w_kdl);
    GETP(quh, w_quh); GETP(qul, w_qul); GETP(kuh, w_kuh); GETP(kul, w_kul);
    GETP(vuh, w_vuh); GETP(vul, w_vul); GETP(woh, w_oh); GETP(wol, w_ol);
    GETP(sgh, w_sgh); GETP(sgl, w_sgl); GETP(suh, w_suh); GETP(sul, w_sul);
    GETP(sdh, w_sdh); GETP(sdl, w_sdl); GETP(rgh, w_rgh); GETP(rgl, w_rgl);
    GETP(ruh, w_ruh); GETP(rul, w_rul); GETP(rdh, w_rdh); GETP(rdl, w_rdl);

    const int SM_BG = 2 * BG_STAGE;   // 110592
    const int SM_BD = 2 * BD_STAGE;   // 110592
    const int SM_SG = NST * SG_STAGE; // 61440
    const int SM_SD = NST * SD_STAGE; // 61440
    cudaFuncSetAttribute(gemm_big<0>, cudaFuncAttributeMaxDynamicSharedMemorySize, SM_BG);
    cudaFuncSetAttribute(gemm_big<5>, cudaFuncAttributeMaxDynamicSharedMemorySize, SM_BG);
    cudaFuncSetAttribute(dual_big<1>, cudaFuncAttributeMaxDynamicSharedMemorySize, SM_BD);
    cudaFuncSetAttribute(dual_big<2>, cudaFuncAttributeMaxDynamicSharedMemorySize, SM_BD);
    cudaFuncSetAttribute(gemm_sm<1>, cudaFuncAttributeMaxDynamicSharedMemorySize, SM_SG);
    cudaFuncSetAttribute(gemm_sm<2>, cudaFuncAttributeMaxDynamicSharedMemorySize, SM_SG);
    cudaFuncSetAttribute(dual_sm, cudaFuncAttributeMaxDynamicSharedMemorySize, SM_SD);
    cudaFuncSetAttribute(attn_mma, cudaFuncAttributeMaxDynamicSharedMemorySize, ATTN_SMEM);

    auto cvt = [&](const float* S, hf* H, hf* L, int R, int K, int Rp, int Kp) {
        long total8 = (long)Rp * Kp / 8;
        cvt_w8<<<(int)((total8 + 255) / 256), 256>>>(S, H, L, R, K, Kp, total8);
    };

    const int MB = T_TOK / 128;  // 64

    cvt(Wqd, qdh, qdl, 144, 576, 256, 576);
    cvt(Wkvd, kdh, kdl, 144, 576, 256, 576);
    rmsnorm_kernel<<<T_TOK, 192>>>(x, ln1w, nullptr, ph);
    dual_sm<<<dim3(6, MB), NTH, SM_SD>>>(ph, qdh, qdl, kdh, kdl,
                                         pql, pkv, LATP, LAT, 18);

    zero_cnt_kernel<<<1, 32>>>();
    init_entries_kernel<<<(ENT_CAP + 255) / 256, 256>>>();
    cvt(Wqu, quh, qul, 576, 144, 640, 192);
    cvt(Wku, kuh, kul, 576, 144, 640, 192);
    cvt(Wvu, vuh, vul, 576, 144, 640, 192);
    cvt(Wo, woh, wol, 576, 576, 640, 576);
    cvt(sg, sgh, sgl, 1536, 576, 1536, 576);
    cvt(su, suh, sul, 1536, 576, 1536, 576);
    cvt(sd, sdh, sdl, 576, 1536, 640, 1536);
    cvt(rg, rgh, rgl, NE * 1536, 576, NE * 1536, 576);
    cvt(ru, ruh, rul, NE * 1536, 576, NE * 1536, 576);
    for (int e = 0; e < NE; ++e)
        cvt(rd + (long)e * 576 * 1536, rdh + (long)e * 640 * 1536, rdl + (long)e * 640 * 1536,
            576, 1536, 640, 1536);

    gemm_sm<2><<<dim3(9, MB), NTH, SM_SG>>>(pql, quh, qul, nullptr, nullptr,
                                            paq, D_MOD, D_MOD, 6);
    dual_sm<<<dim3(18, MB), NTH, SM_SD>>>(pkv, kuh, kul, vuh, vul,
                                          pak, pav, D_MOD, D_MOD, 6);

    rope_kernel<<<T_TOK, 288>>>(paq, pak);

    attn_mma<<<dim3(SEQ / 128, 8 * N_HEAD), ATH, ATTN_SMEM>>>(paq, pak, pav, po);

    gemm_sm<1><<<dim3(9, MB), NTH, SM_SG>>>(po, woh, wol, px2, x,
                                            nullptr, 0, D_MOD, 18);

    rmsnorm_kernel<<<T_TOK, 192>>>(px2, ln2w, ph2f, ph2);

    dual_big<1><<<dim3(FF / 64, MB), NTH, SM_BD>>>(ph2, sgh, sgl, suh, sul,
                                                   pff, FF, 9, 0);
    gemm_big<0><<<dim3(5, MB), NTH, SM_BG>>>(pff, sdh, sdl, pshared,
                                             D_MOD, 24, 0);

    router_kernel<<<T_TOK, 256>>>(ph2f, Wr, rb);
    offsets_kernel<<<1, 1>>>();
    scatter_kernel<<<T_TOK / 256, 256>>>();

    const int EB = ENT_CAP / 128;  // 135
    dual_big<2><<<dim3(FF / 64, EB), NTH, SM_BD>>>(ph2, rgh, rgl, ruh, rul,
                                                   pe, FF, 9, (long)FF * D_MOD);
    gemm_big<5><<<dim3(5, EB), NTH, SM_BG>>>(pe, rdh, rdl, nullptr,
                                             D_MOD, 24, (long)640 * FF);

    combine_kernel<<<T_TOK, 192>>>(out);
}